// round 1
// baseline (speedup 1.0000x reference)
#include <cuda_runtime.h>

// FeedForwardQuantum: out = relu(cos(x+theta) @ W1 + b1) @ W2 + b2
// x: [B*S, 8] fp32 (524288 rows), W1: [8,32], W2: [32,8].
// Strategy: 4 rows per thread packed as 2x f32x2; all GEMM FMAs are
// fma.rn.f32x2 (FFMA2) with weights pre-duplicated (w,w) in SMEM.

#define EDIM 8
#define FDIM 32
#define RPT 4      // rows per thread (two f32x2 pairs)
#define BLOCK 128

// packed f32x2 fma: d = a*b + c (elementwise on both lanes)
__device__ __forceinline__ float2 ffma2(float2 a, float2 b, float2 c) {
    float2 d;
    asm("{\n\t"
        ".reg .b64 ra, rb, rc, rd;\n\t"
        "mov.b64 ra, {%2, %3};\n\t"
        "mov.b64 rb, {%4, %5};\n\t"
        "mov.b64 rc, {%6, %7};\n\t"
        "fma.rn.f32x2 rd, ra, rb, rc;\n\t"
        "mov.b64 {%0, %1}, rd;\n\t"
        "}"
        : "=f"(d.x), "=f"(d.y)
        : "f"(a.x), "f"(a.y), "f"(b.x), "f"(b.y), "f"(c.x), "f"(c.y));
    return d;
}

// accurate-enough cos for |a| <~ 16: 2-term 2pi reduction + MUFU cos
__device__ __forceinline__ float fast_cos(float a) {
    const float INV_2PI = 0.15915494309189535f;
    const float PI2_HI  = 6.28318548202514648f;   // float(2*pi)
    const float PI2_LO  = 1.7484555e-7f;          // float(2*pi) - 2*pi (compensation)
    float k = rintf(a * INV_2PI);
    float r = fmaf(k, -PI2_HI, a);
    r = fmaf(k, PI2_LO, r);
    return __cosf(r);
}

__global__ void __launch_bounds__(BLOCK)
ffq_kernel(const float* __restrict__ x, const float* __restrict__ theta,
           const float* __restrict__ w1, const float* __restrict__ b1,
           const float* __restrict__ w2, const float* __restrict__ b2,
           float* __restrict__ out, long long nrows)
{
    // duplicated-pair weights: each entry holds (w, w) so a single LDS feeds FFMA2
    __shared__ float2 s_w1[FDIM][EDIM];   // [f][e] = dup(w1[e][f])  (transposed)
    __shared__ float2 s_w2[FDIM][EDIM];   // [f][e] = dup(w2[f][e])
    __shared__ float2 s_b1[FDIM];
    __shared__ float2 s_b2[EDIM];

    const int t = threadIdx.x;
    for (int i = t; i < FDIM * EDIM; i += BLOCK) {
        int f = i / EDIM, e = i % EDIM;
        float v1 = w1[e * FDIM + f];
        s_w1[f][e] = make_float2(v1, v1);
        float v2 = w2[f * EDIM + e];
        s_w2[f][e] = make_float2(v2, v2);
    }
    if (t < FDIM) { float v = b1[t]; s_b1[t] = make_float2(v, v); }
    if (t < EDIM) { float v = b2[t]; s_b2[t] = make_float2(v, v); }
    __syncthreads();

    const long long idx  = (long long)blockIdx.x * BLOCK + t;
    const long long row0 = idx * RPT;
    if (row0 >= nrows) return;

    float th[EDIM];
#pragma unroll
    for (int e = 0; e < EDIM; e++) th[e] = __ldg(theta + e);

    if (row0 + RPT <= nrows) {
        // ---- fast path: 4 full rows ----
        const float4* xp = reinterpret_cast<const float4*>(x + row0 * EDIM);
        float4 xv[RPT * 2];
#pragma unroll
        for (int i = 0; i < RPT * 2; i++) xv[i] = xp[i];

        float qs[RPT][EDIM];
#pragma unroll
        for (int r = 0; r < RPT; r++) {
            const float* vr = reinterpret_cast<const float*>(&xv[r * 2]);
#pragma unroll
            for (int e = 0; e < EDIM; e++) qs[r][e] = fast_cos(vr[e] + th[e]);
        }

        float2 q01[EDIM], q23[EDIM];
#pragma unroll
        for (int e = 0; e < EDIM; e++) {
            q01[e] = make_float2(qs[0][e], qs[1][e]);
            q23[e] = make_float2(qs[2][e], qs[3][e]);
        }

        float2 acc01[EDIM], acc23[EDIM];
#pragma unroll
        for (int e = 0; e < EDIM; e++) { acc01[e] = s_b2[e]; acc23[e] = s_b2[e]; }

#pragma unroll
        for (int f = 0; f < FDIM; f++) {
            // vector-load the duplicated weight rows (forces LDS.128)
            const float4* w1p = reinterpret_cast<const float4*>(&s_w1[f][0]);
            const float4* w2p = reinterpret_cast<const float4*>(&s_w2[f][0]);
            float4 wa = w1p[0], wb = w1p[1], wc = w1p[2], wd = w1p[3];

            float2 h01 = s_b1[f], h23 = s_b1[f];
            float2 wpair;
            wpair = make_float2(wa.x, wa.y); h01 = ffma2(q01[0], wpair, h01); h23 = ffma2(q23[0], wpair, h23);
            wpair = make_float2(wa.z, wa.w); h01 = ffma2(q01[1], wpair, h01); h23 = ffma2(q23[1], wpair, h23);
            wpair = make_float2(wb.x, wb.y); h01 = ffma2(q01[2], wpair, h01); h23 = ffma2(q23[2], wpair, h23);
            wpair = make_float2(wb.z, wb.w); h01 = ffma2(q01[3], wpair, h01); h23 = ffma2(q23[3], wpair, h23);
            wpair = make_float2(wc.x, wc.y); h01 = ffma2(q01[4], wpair, h01); h23 = ffma2(q23[4], wpair, h23);
            wpair = make_float2(wc.z, wc.w); h01 = ffma2(q01[5], wpair, h01); h23 = ffma2(q23[5], wpair, h23);
            wpair = make_float2(wd.x, wd.y); h01 = ffma2(q01[6], wpair, h01); h23 = ffma2(q23[6], wpair, h23);
            wpair = make_float2(wd.z, wd.w); h01 = ffma2(q01[7], wpair, h01); h23 = ffma2(q23[7], wpair, h23);

            h01.x = fmaxf(h01.x, 0.0f); h01.y = fmaxf(h01.y, 0.0f);
            h23.x = fmaxf(h23.x, 0.0f); h23.y = fmaxf(h23.y, 0.0f);

            float4 va = w2p[0], vb = w2p[1], vc = w2p[2], vd = w2p[3];
            wpair = make_float2(va.x, va.y); acc01[0] = ffma2(h01, wpair, acc01[0]); acc23[0] = ffma2(h23, wpair, acc23[0]);
            wpair = make_float2(va.z, va.w); acc01[1] = ffma2(h01, wpair, acc01[1]); acc23[1] = ffma2(h23, wpair, acc23[1]);
            wpair = make_float2(vb.x, vb.y); acc01[2] = ffma2(h01, wpair, acc01[2]); acc23[2] = ffma2(h23, wpair, acc23[2]);
            wpair = make_float2(vb.z, vb.w); acc01[3] = ffma2(h01, wpair, acc01[3]); acc23[3] = ffma2(h23, wpair, acc23[3]);
            wpair = make_float2(vc.x, vc.y); acc01[4] = ffma2(h01, wpair, acc01[4]); acc23[4] = ffma2(h23, wpair, acc23[4]);
            wpair = make_float2(vc.z, vc.w); acc01[5] = ffma2(h01, wpair, acc01[5]); acc23[5] = ffma2(h23, wpair, acc23[5]);
            wpair = make_float2(vd.x, vd.y); acc01[6] = ffma2(h01, wpair, acc01[6]); acc23[6] = ffma2(h23, wpair, acc23[6]);
            wpair = make_float2(vd.z, vd.w); acc01[7] = ffma2(h01, wpair, acc01[7]); acc23[7] = ffma2(h23, wpair, acc23[7]);
        }

        float4* op = reinterpret_cast<float4*>(out + row0 * EDIM);
        float4 o[RPT * 2];
        o[0] = make_float4(acc01[0].x, acc01[1].x, acc01[2].x, acc01[3].x);
        o[1] = make_float4(acc01[4].x, acc01[5].x, acc01[6].x, acc01[7].x);
        o[2] = make_float4(acc01[0].y, acc01[1].y, acc01[2].y, acc01[3].y);
        o[3] = make_float4(acc01[4].y, acc01[5].y, acc01[6].y, acc01[7].y);
        o[4] = make_float4(acc23[0].x, acc23[1].x, acc23[2].x, acc23[3].x);
        o[5] = make_float4(acc23[4].x, acc23[5].x, acc23[6].x, acc23[7].x);
        o[6] = make_float4(acc23[0].y, acc23[1].y, acc23[2].y, acc23[3].y);
        o[7] = make_float4(acc23[4].y, acc23[5].y, acc23[6].y, acc23[7].y);
#pragma unroll
        for (int i = 0; i < RPT * 2; i++) op[i] = o[i];
    } else {
        // ---- tail: scalar per-row fallback ----
        for (long long r = row0; r < nrows; r++) {
            float q[EDIM];
#pragma unroll
            for (int e = 0; e < EDIM; e++) q[e] = fast_cos(x[r * EDIM + e] + th[e]);
            float o[EDIM];
#pragma unroll
            for (int e = 0; e < EDIM; e++) o[e] = s_b2[e].x;
            for (int f = 0; f < FDIM; f++) {
                float h = s_b1[f].x;
#pragma unroll
                for (int e = 0; e < EDIM; e++) h = fmaf(q[e], s_w1[f][e].x, h);
                h = fmaxf(h, 0.0f);
#pragma unroll
                for (int e = 0; e < EDIM; e++) o[e] = fmaf(h, s_w2[f][e].x, o[e]);
            }
#pragma unroll
            for (int e = 0; e < EDIM; e++) out[r * EDIM + e] = o[e];
        }
    }
}

extern "C" void kernel_launch(void* const* d_in, const int* in_sizes, int n_in,
                              void* d_out, int out_size) {
    const float* x     = (const float*)d_in[0];
    const float* theta = (const float*)d_in[1];
    const float* w1    = (const float*)d_in[2];
    const float* b1    = (const float*)d_in[3];
    const float* w2    = (const float*)d_in[4];
    const float* b2    = (const float*)d_in[5];
    float* out = (float*)d_out;

    long long nrows = (long long)in_sizes[0] / EDIM;
    long long nthreads = (nrows + RPT - 1) / RPT;
    int blocks = (int)((nthreads + BLOCK - 1) / BLOCK);

    ffq_kernel<<<blocks, BLOCK>>>(x, theta, w1, b1, w2, b2, out, nrows);
}

// round 2
// speedup vs baseline: 1.2775x; 1.2775x over previous
#include <cuda_runtime.h>

// FeedForwardQuantum: out = relu(cos(x+theta) @ W1 + b1) @ W2 + b2
// x: [524288, 8] fp32, W1: [8,32], W2: [32,8].
// R1 finding: duplicated-weight SMEM scheme was LDS-wavefront bound (L1=63%).
// R2: weights via constant port (LDC.128), f-major packed, non-duplicated;
// (w,w) FFMA2 pairs built in-register on the alu pipe.

#define EDIM 8
#define FDIM 32
#define RPT 4      // rows per thread (two f32x2 pairs)
#define BLOCK 128

struct CW {
    float4 wf[FDIM * 4];  // per f: [w1col e0-3][w1col e4-7][w2row e0-3][w2row e4-7]
    float  b1[FDIM];
    float  b2[EDIM];
};

__constant__ CW c_w;     // read by main kernel via constant port
__device__   CW g_s;     // scratch filled by prep kernel, memcpy'd into c_w

// packed f32x2 fma: d = a*b + c (elementwise on both lanes)
__device__ __forceinline__ float2 ffma2(float2 a, float2 b, float2 c) {
    float2 d;
    asm("{\n\t"
        ".reg .b64 ra, rb, rc, rd;\n\t"
        "mov.b64 ra, {%2, %3};\n\t"
        "mov.b64 rb, {%4, %5};\n\t"
        "mov.b64 rc, {%6, %7};\n\t"
        "fma.rn.f32x2 rd, ra, rb, rc;\n\t"
        "mov.b64 {%0, %1}, rd;\n\t"
        "}"
        : "=f"(d.x), "=f"(d.y)
        : "f"(a.x), "f"(a.y), "f"(b.x), "f"(b.y), "f"(c.x), "f"(c.y));
    return d;
}

// accurate-enough cos for |a| <~ 16: 2-term 2pi reduction + MUFU cos
__device__ __forceinline__ float fast_cos(float a) {
    const float INV_2PI = 0.15915494309189535f;
    const float PI2_HI  = 6.28318548202514648f;   // float(2*pi)
    const float PI2_LO  = 1.7484555e-7f;          // float(2*pi) - 2*pi (compensation)
    float k = rintf(a * INV_2PI);
    float r = fmaf(k, -PI2_HI, a);
    r = fmaf(k, PI2_LO, r);
    return __cosf(r);
}

__global__ void ffq_prep(const float* __restrict__ w1, const float* __restrict__ b1,
                         const float* __restrict__ w2, const float* __restrict__ b2)
{
    int f = threadIdx.x;
    if (f < FDIM) {
        // w1 is [E][F] row-major; gather column f (8 floats)
        g_s.wf[f * 4 + 0] = make_float4(w1[0 * FDIM + f], w1[1 * FDIM + f],
                                        w1[2 * FDIM + f], w1[3 * FDIM + f]);
        g_s.wf[f * 4 + 1] = make_float4(w1[4 * FDIM + f], w1[5 * FDIM + f],
                                        w1[6 * FDIM + f], w1[7 * FDIM + f]);
        // w2 is [F][E] row-major; row f is contiguous (8 floats)
        const float4* w2v = reinterpret_cast<const float4*>(w2);
        g_s.wf[f * 4 + 2] = w2v[f * 2 + 0];
        g_s.wf[f * 4 + 3] = w2v[f * 2 + 1];
        g_s.b1[f] = b1[f];
        if (f < EDIM) g_s.b2[f] = b2[f];
    }
}

__global__ void __launch_bounds__(BLOCK)
ffq_kernel(const float* __restrict__ x, const float* __restrict__ theta,
           float* __restrict__ out, long long nrows)
{
    const int t = threadIdx.x;
    const long long idx  = (long long)blockIdx.x * BLOCK + t;
    const long long row0 = idx * RPT;
    if (row0 >= nrows) return;

    float th[EDIM];
#pragma unroll
    for (int e = 0; e < EDIM; e++) th[e] = __ldg(theta + e);

    if (row0 + RPT <= nrows) {
        // ---- fast path: 4 full rows ----
        const float4* xp = reinterpret_cast<const float4*>(x + row0 * EDIM);
        float4 xv[RPT * 2];
#pragma unroll
        for (int i = 0; i < RPT * 2; i++) xv[i] = xp[i];

        float qs[RPT][EDIM];
#pragma unroll
        for (int r = 0; r < RPT; r++) {
            const float* vr = reinterpret_cast<const float*>(&xv[r * 2]);
#pragma unroll
            for (int e = 0; e < EDIM; e++) qs[r][e] = fast_cos(vr[e] + th[e]);
        }

        float2 q01[EDIM], q23[EDIM];
#pragma unroll
        for (int e = 0; e < EDIM; e++) {
            q01[e] = make_float2(qs[0][e], qs[1][e]);
            q23[e] = make_float2(qs[2][e], qs[3][e]);
        }

        float2 acc01[EDIM], acc23[EDIM];
#pragma unroll
        for (int e = 0; e < EDIM; e++) {
            float b = c_w.b2[e];
            acc01[e] = make_float2(b, b);
            acc23[e] = make_float2(b, b);
        }

#pragma unroll
        for (int f = 0; f < FDIM; f++) {
            // non-duplicated weights via constant port (LDC.128)
            float4 wa = c_w.wf[f * 4 + 0];   // w1[e0..3][f]
            float4 wb = c_w.wf[f * 4 + 1];   // w1[e4..7][f]
            float  bf = c_w.b1[f];

            float2 h01 = make_float2(bf, bf), h23 = h01;
            float2 wp;
            wp = make_float2(wa.x, wa.x); h01 = ffma2(q01[0], wp, h01); h23 = ffma2(q23[0], wp, h23);
            wp = make_float2(wa.y, wa.y); h01 = ffma2(q01[1], wp, h01); h23 = ffma2(q23[1], wp, h23);
            wp = make_float2(wa.z, wa.z); h01 = ffma2(q01[2], wp, h01); h23 = ffma2(q23[2], wp, h23);
            wp = make_float2(wa.w, wa.w); h01 = ffma2(q01[3], wp, h01); h23 = ffma2(q23[3], wp, h23);
            wp = make_float2(wb.x, wb.x); h01 = ffma2(q01[4], wp, h01); h23 = ffma2(q23[4], wp, h23);
            wp = make_float2(wb.y, wb.y); h01 = ffma2(q01[5], wp, h01); h23 = ffma2(q23[5], wp, h23);
            wp = make_float2(wb.z, wb.z); h01 = ffma2(q01[6], wp, h01); h23 = ffma2(q23[6], wp, h23);
            wp = make_float2(wb.w, wb.w); h01 = ffma2(q01[7], wp, h01); h23 = ffma2(q23[7], wp, h23);

            h01.x = fmaxf(h01.x, 0.0f); h01.y = fmaxf(h01.y, 0.0f);
            h23.x = fmaxf(h23.x, 0.0f); h23.y = fmaxf(h23.y, 0.0f);

            float4 va = c_w.wf[f * 4 + 2];   // w2[f][e0..3]
            float4 vb = c_w.wf[f * 4 + 3];   // w2[f][e4..7]
            wp = make_float2(va.x, va.x); acc01[0] = ffma2(h01, wp, acc01[0]); acc23[0] = ffma2(h23, wp, acc23[0]);
            wp = make_float2(va.y, va.y); acc01[1] = ffma2(h01, wp, acc01[1]); acc23[1] = ffma2(h23, wp, acc23[1]);
            wp = make_float2(va.z, va.z); acc01[2] = ffma2(h01, wp, acc01[2]); acc23[2] = ffma2(h23, wp, acc23[2]);
            wp = make_float2(va.w, va.w); acc01[3] = ffma2(h01, wp, acc01[3]); acc23[3] = ffma2(h23, wp, acc23[3]);
            wp = make_float2(vb.x, vb.x); acc01[4] = ffma2(h01, wp, acc01[4]); acc23[4] = ffma2(h23, wp, acc23[4]);
            wp = make_float2(vb.y, vb.y); acc01[5] = ffma2(h01, wp, acc01[5]); acc23[5] = ffma2(h23, wp, acc23[5]);
            wp = make_float2(vb.z, vb.z); acc01[6] = ffma2(h01, wp, acc01[6]); acc23[6] = ffma2(h23, wp, acc23[6]);
            wp = make_float2(vb.w, vb.w); acc01[7] = ffma2(h01, wp, acc01[7]); acc23[7] = ffma2(h23, wp, acc23[7]);
        }

        float4* op = reinterpret_cast<float4*>(out + row0 * EDIM);
        float4 o[RPT * 2];
        o[0] = make_float4(acc01[0].x, acc01[1].x, acc01[2].x, acc01[3].x);
        o[1] = make_float4(acc01[4].x, acc01[5].x, acc01[6].x, acc01[7].x);
        o[2] = make_float4(acc01[0].y, acc01[1].y, acc01[2].y, acc01[3].y);
        o[3] = make_float4(acc01[4].y, acc01[5].y, acc01[6].y, acc01[7].y);
        o[4] = make_float4(acc23[0].x, acc23[1].x, acc23[2].x, acc23[3].x);
        o[5] = make_float4(acc23[4].x, acc23[5].x, acc23[6].x, acc23[7].x);
        o[6] = make_float4(acc23[0].y, acc23[1].y, acc23[2].y, acc23[3].y);
        o[7] = make_float4(acc23[4].y, acc23[5].y, acc23[6].y, acc23[7].y);
#pragma unroll
        for (int i = 0; i < RPT * 2; i++) op[i] = o[i];
    } else {
        // ---- tail: scalar per-row fallback ----
        for (long long r = row0; r < nrows; r++) {
            float q[EDIM];
#pragma unroll
            for (int e = 0; e < EDIM; e++) q[e] = fast_cos(x[r * EDIM + e] + th[e]);
            float o[EDIM];
#pragma unroll
            for (int e = 0; e < EDIM; e++) o[e] = c_w.b2[e];
            for (int f = 0; f < FDIM; f++) {
                float h = c_w.b1[f];
                const float* w1c = reinterpret_cast<const float*>(&c_w.wf[f * 4 + 0]);
                const float* w2r = reinterpret_cast<const float*>(&c_w.wf[f * 4 + 2]);
#pragma unroll
                for (int e = 0; e < EDIM; e++) h = fmaf(q[e], w1c[e], h);
                h = fmaxf(h, 0.0f);
#pragma unroll
                for (int e = 0; e < EDIM; e++) o[e] = fmaf(h, w2r[e], o[e]);
            }
#pragma unroll
            for (int e = 0; e < EDIM; e++) out[r * EDIM + e] = o[e];
        }
    }
}

extern "C" void kernel_launch(void* const* d_in, const int* in_sizes, int n_in,
                              void* d_out, int out_size) {
    const float* x     = (const float*)d_in[0];
    const float* theta = (const float*)d_in[1];
    const float* w1    = (const float*)d_in[2];
    const float* b1    = (const float*)d_in[3];
    const float* w2    = (const float*)d_in[4];
    const float* b2    = (const float*)d_in[5];
    float* out = (float*)d_out;

    long long nrows = (long long)in_sizes[0] / EDIM;
    long long nthreads = (nrows + RPT - 1) / RPT;
    int blocks = (int)((nthreads + BLOCK - 1) / BLOCK);

    // 1) pack weights (transpose w1, interleave with w2) into device scratch
    ffq_prep<<<1, 64>>>(w1, b1, w2, b2);

    // 2) graph-legal D2D copy scratch -> __constant__ symbol
    void *c_ptr = nullptr, *s_ptr = nullptr;
    cudaGetSymbolAddress(&c_ptr, c_w);
    cudaGetSymbolAddress(&s_ptr, g_s);
    cudaMemcpyAsync(c_ptr, s_ptr, sizeof(CW), cudaMemcpyDeviceToDevice, 0);

    // 3) main kernel reads weights via the constant port
    ffq_kernel<<<blocks, BLOCK>>>(x, theta, out, nrows);
}